// round 12
// baseline (speedup 1.0000x reference)
#include <cuda_runtime.h>

#define NN   116
#define NE   6670
#define HID  64
#define ENCD 122

// ---- device scratch ----
__device__ float g_gE[NE * 5];
__device__ float g_dv[NN];
__device__ __align__(16) float g_x1[NN * HID];
__device__ __align__(16) float g_Wc[HID * 4];    // W2 @ Wl
__device__ float g_S[NN * 5];
__device__ unsigned g_epoch = 0;                 // bumped once per k1 launch
__device__ unsigned g_Sflag[NN];                 // g_Sflag[i]==epoch => S[i] ready

__device__ __forceinline__ int rowoff(int a) { return a * (231 - a) / 2; }
__device__ __forceinline__ int eix(int a, int b) { return rowoff(a) + (b - a - 1); }

// ============================================================================
// K1 (118 x 512): blocks 0..115 per-node x1/dv (all global loads batched up
// front, float2 enc loads); block 116: Wc = W2@Wl; block 117: bias seed + epoch.
// ============================================================================
__global__ void __launch_bounds__(512, 1) k1(
    const float* __restrict__ enc, const float* __restrict__ ea,
    const float* __restrict__ W_enc, const float* __restrict__ b_enc,
    const float* __restrict__ W1, const float* __restrict__ b1,
    const float* __restrict__ p1, const float* __restrict__ We,
    const float* __restrict__ pe, const float* __restrict__ W2,
    const float* __restrict__ b2, const float* __restrict__ Wl,
    const float* __restrict__ bl, float* __restrict__ out)
{
    const int i = blockIdx.x, t = threadIdx.x;

    if (i >= NN) {
        if (i == NN) {                   // Wc = W2 @ Wl (256 outputs)
            if (t < 256) {
                int k = t >> 2, o = t & 3;
                float s = 0.f;
                #pragma unroll
                for (int m = 0; m < HID; m++) s += W2[k * HID + m] * Wl[m * 4 + o];
                g_Wc[t] = s;
            }
        } else {                         // bias seed + epoch bump
            if (t < 4) {
                float v = bl[t];
                #pragma unroll
                for (int m = 0; m < HID; m++) v += b2[m] * Wl[m * 4 + t];
                out[t] = v;
            }
            if (t == 8) atomicAdd(&g_epoch, 1u);
        }
        return;
    }

    __shared__ float sd1[120];           // [115..119] zero pad
    __shared__ float sMp[8 * 123];
    __shared__ float sM[128];            // [122]=s_i bias lane, [123..127]=0
    __shared__ float sp[512];
    __shared__ float sy[64];
    __shared__ float sx1[64];

    const int g = t >> 6, m = t & 63;    // y/x1-stage ids
    const int c2 = t >> 3, q8 = t & 7;   // M-stage: column pair c2, 8-way split
    const bool mA = (c2 < 61);

    // ---------- Phase 0: batch-issue ALL global loads ----------
    float a5[5];
    int eg = 0, ka = 0;
    const bool edge_act = t < 115;
    if (edge_act) {
        int k = t + (t >= i);
        ka = min(i, k);
        int kb = max(i, k);
        eg = eix(ka, kb);
        const float* A = ea + eg * 5;
        #pragma unroll
        for (int c = 0; c < 5; c++) a5[c] = A[c];
    }
    // M-stage enc operands: 15 float2 per thread (cols 2c2, 2c2+1)
    float2 rE2[15];
    #pragma unroll
    for (int j = 0; j < 15; ++j) {
        int u = q8 * 15 + j;
        float2 v = make_float2(0.f, 0.f);
        if (mA && u < 115) {
            int k = u + (u >= i);
            v = *reinterpret_cast<const float2*>(enc + k * ENCD + 2 * c2);
        }
        rE2[j] = v;
    }
    // y-stage weights (16 per thread): operand [W_enc; b_enc; 0]
    float rWz[16];
    #pragma unroll
    for (int j = 0; j < 16; ++j) {
        int c = g * 16 + j;
        rWz[j] = (c < 122) ? W_enc[c * HID + m] : ((c == 122) ? b_enc[m] : 0.f);
    }
    // x1-stage weights (8 per thread)
    float rW1[8];
    #pragma unroll
    for (int j = 0; j < 8; ++j) rW1[j] = W1[(g * 8 + j) * HID + m];
    float rb1 = (t < 64) ? b1[t] : 0.f;
    float rpe0 = 0.f, rpe1 = 0.f;
    if (t < 32) { rpe0 = pe[t]; rpe1 = pe[t + 32]; }

    // ---------- d1 + gE ----------
    if (edge_act) {
        float r5[5];
        #pragma unroll
        for (int c = 0; c < 5; c++) r5[c] = fmaxf(a5[c], 0.f);
        sd1[t] = a5[0] * __ldg(&p1[0]) + a5[1] * __ldg(&p1[1]) + a5[2] * __ldg(&p1[2])
               + a5[3] * __ldg(&p1[3]) + a5[4] * __ldg(&p1[4]);
        if (ka == i) {
            #pragma unroll
            for (int c2b = 0; c2b < 5; c2b++) {
                float gg = r5[0] * __ldg(&We[c2b]) + r5[1] * __ldg(&We[5 + c2b])
                         + r5[2] * __ldg(&We[10 + c2b]) + r5[3] * __ldg(&We[15 + c2b])
                         + r5[4] * __ldg(&We[20 + c2b]);
                g_gE[eg * 5 + c2b] = gg;
            }
        }
    }
    if (t >= 115 && t < 120) sd1[t] = 0.f;
    __syncthreads();

    // ---------- M stage (float2 pairs, 8-way split) ----------
    if (mA) {
        float s0 = 0.f, s1 = 0.f;
        #pragma unroll
        for (int j = 0; j < 15; ++j) {
            float d = sd1[q8 * 15 + j];
            s0 += rE2[j].x * d;
            s1 += rE2[j].y * d;
        }
        sMp[q8 * 123 + 2 * c2]     = s0;
        sMp[q8 * 123 + 2 * c2 + 1] = s1;
    } else if (c2 == 61) {               // bias lane: plain sum of d1
        float s = 0.f;
        #pragma unroll
        for (int j = 0; j < 15; ++j) {
            int u = q8 * 15 + j;
            if (u < 115) s += sd1[u];
        }
        sMp[q8 * 123 + 122] = s;
    }
    __syncthreads();
    if (t < 123) {
        float s = 0.f;
        #pragma unroll
        for (int q = 0; q < 8; ++q) s += sMp[q * 123 + t];
        sM[t] = s;
    }
    if (t >= 123 && t < 128) sM[t] = 0.f;
    __syncthreads();

    // ---------- y = M @ [W_enc; b_enc; 0] ----------
    {
        float s = 0.f;
        #pragma unroll
        for (int j = 0; j < 16; ++j) s += sM[g * 16 + j] * rWz[j];
        sp[g * 64 + m] = s;
    }
    __syncthreads();
    if (t < HID) {
        float s = sp[t];
        #pragma unroll
        for (int gg = 1; gg < 8; ++gg) s += sp[gg * 64 + t];
        sy[t] = s;
    }
    __syncthreads();

    // ---------- x1 = relu(b1 + y @ W1) ----------
    {
        float s = 0.f;
        #pragma unroll
        for (int j = 0; j < 8; ++j) s += sy[g * 8 + j] * rW1[j];
        sp[g * 64 + m] = s;
    }
    __syncthreads();
    if (t < HID) {
        float s = sp[t];
        #pragma unroll
        for (int gg = 1; gg < 8; ++gg) s += sp[gg * 64 + t];
        float x = fmaxf(rb1 + s, 0.f);
        sx1[t] = x;
        g_x1[i * HID + t] = x;
    }
    __syncthreads();

    // ---------- dv = x1 . pe ----------
    if (t < 32) {
        float s = sx1[t] * rpe0 + sx1[t + 32] * rpe1;
        #pragma unroll
        for (int off = 16; off; off >>= 1) s += __shfl_xor_sync(0xffffffffu, s, off);
        if (t == 0) g_dv[i] = s;
    }
}

// ============================================================================
// K23 (PDL, 116 x 128): Phase A: S[i] -> flag[i]=epoch. Spin on all flags.
// Phase B: D[i] (reusing phase-A registers), q = x1@Wc, atomic out.
// ============================================================================
__global__ void __launch_bounds__(128, 1) k23(
    const float* __restrict__ be, const float* __restrict__ p2,
    float* __restrict__ out)
{
    cudaGridDependencySynchronize();     // k1 done: dv, gE, x1, Wc, seed valid

    __shared__ float sdv[NN];
    __shared__ float sS[NN * 5];
    __shared__ float sx1r[HID];
    __shared__ float sWc[HID * 4];
    __shared__ float wsum[4 * 5];
    __shared__ float wred[4];
    const int i = blockIdx.x, t = threadIdx.x;
    const int wq = t >> 5, lane = t & 31;
    const unsigned E = *(volatile unsigned*)&g_epoch;

    // ---- Phase A batch loads: gE row, dv, plus phase-B operands ----
    float a5[5] = {0.f, 0.f, 0.f, 0.f, 0.f};
    int kn = 0;
    if (t < 115) {
        kn = t + (t >= i);
        int a = min(i, kn), b = max(i, kn);
        int e = eix(a, b);
        #pragma unroll
        for (int c = 0; c < 5; c++) a5[c] = g_gE[e * 5 + c];
    }
    if (t < NN) sdv[t] = g_dv[t];
    if (t < HID) sx1r[t] = g_x1[i * HID + t];
    sWc[t] = g_Wc[t];
    sWc[t + 128] = g_Wc[t + 128];
    float rbe[5], rp2[5];
    #pragma unroll
    for (int c = 0; c < 5; c++) { rbe[c] = __ldg(&be[c]); rp2[c] = __ldg(&p2[c]); }
    __syncthreads();

    // ---- S[i] ----
    float inv = 0.f;
    float s5[5] = {0.f, 0.f, 0.f, 0.f, 0.f};
    if (t < 115) {
        inv = 1.f / (fmaxf(fmaxf(sdv[i], sdv[kn]), 0.f) + 1e-10f);
        #pragma unroll
        for (int c = 0; c < 5; c++) s5[c] = a5[c] * inv;
    }
    #pragma unroll
    for (int c = 0; c < 5; c++) {
        float v = s5[c];
        #pragma unroll
        for (int off = 16; off; off >>= 1) v += __shfl_xor_sync(0xffffffffu, v, off);
        if (lane == 0) wsum[wq * 5 + c] = v;
    }
    __syncthreads();
    if (t < 5) g_S[i * 5 + t] = wsum[t] + wsum[5 + t] + wsum[10 + t] + wsum[15 + t];
    __syncthreads();
    if (t == 0) {
        __threadfence();                 // release S before flag
        g_Sflag[i] = E;
    }

    // ---- wait for all S (parallel single-writer flags; all blocks resident) ----
    if (t < NN) {
        while (*(volatile unsigned*)&g_Sflag[t] != E) {}
    }
    __syncthreads();
    __threadfence();                     // acquire

    if (t < NN) {
        #pragma unroll
        for (int c = 0; c < 5; c++) sS[t * 5 + c] = g_S[t * 5 + c];
    }
    __syncthreads();

    // ---- Phase B: D[i] using registers a5/inv/kn from phase A ----
    float dvi = sdv[i];
    float partv = 0.f;
    if (t < 115) {
        float dvk = sdv[kn];
        #pragma unroll
        for (int c = 0; c < 5; c++) {
            float hh = a5[c] * inv;
            float v = dvi * (sS[i * 5 + c] - hh) + dvk * (sS[kn * 5 + c] - hh) + rbe[c];
            partv += fmaxf(v, 0.f) * rp2[c];
        }
    }
    #pragma unroll
    for (int off = 16; off; off >>= 1) partv += __shfl_xor_sync(0xffffffffu, partv, off);
    if (lane == 0) wred[wq] = partv;
    __syncthreads();

    {
        int o = wq;
        float qv = sx1r[lane] * sWc[lane * 4 + o] + sx1r[lane + 32] * sWc[(lane + 32) * 4 + o];
        #pragma unroll
        for (int off = 16; off; off >>= 1) qv += __shfl_xor_sync(0xffffffffu, qv, off);
        if (lane == 0) {
            float D = wred[0] + wred[1] + wred[2] + wred[3];
            atomicAdd(&out[o], D * qv * (1.0f / (float)NN));
        }
    }
}

extern "C" void kernel_launch(void* const* d_in, const int* in_sizes, int n_in,
                              void* d_out, int out_size) {
    const float* enc   = (const float*)d_in[0];
    const float* ea    = (const float*)d_in[1];
    // d_in[2] = edge_index (triu order, closed-form reproduced) — unused
    const float* W_enc = (const float*)d_in[3];
    const float* b_enc = (const float*)d_in[4];
    const float* W1    = (const float*)d_in[5];
    const float* b1    = (const float*)d_in[6];
    const float* p1    = (const float*)d_in[7];
    const float* We    = (const float*)d_in[8];
    const float* be    = (const float*)d_in[9];
    const float* pe    = (const float*)d_in[10];
    const float* W2    = (const float*)d_in[11];
    const float* b2    = (const float*)d_in[12];
    const float* p2    = (const float*)d_in[13];
    const float* Wl    = (const float*)d_in[14];
    const float* bl    = (const float*)d_in[15];
    float* out = (float*)d_out;

    cudaLaunchAttribute attr[1];
    attr[0].id = cudaLaunchAttributeProgrammaticStreamSerialization;
    attr[0].val.programmaticStreamSerializationAllowed = 1;

    k1<<<NN + 2, 512>>>(enc, ea, W_enc, b_enc, W1, b1, p1, We, pe, W2, b2, Wl, bl, out);
    {
        cudaLaunchConfig_t cfg = {};
        cfg.gridDim = dim3(NN); cfg.blockDim = dim3(128);
        cfg.attrs = attr; cfg.numAttrs = 1; cfg.stream = 0;
        cudaLaunchKernelEx(&cfg, k23, be, p2, out);
    }
}